// round 5
// baseline (speedup 1.0000x reference)
#include <cuda_runtime.h>
#include <cuda_bf16.h>

#define NN 50000
#define EE 800000
#define HH 64

// ---------------- device scratch (no allocs allowed) ----------------
__device__ float g_h[NN * HH];
__device__ float g_p[NN * HH];
__device__ float g_EA[NN * HH];
__device__ float g_EB[NN * HH];
__device__ float g_S[NN * HH];
__device__ float g_R[NN * HH];
__device__ float g_agg[NN * HH];
__device__ float g_esum[NN * 16];
__device__ int   g_deg[NN];
__device__ int   g_rowptr[NN + 1];
__device__ int   g_cursor[NN];
__device__ int   g_col[EE];
__device__ float g_EW[16 * HH];
__device__ float g_ec[HH];
__device__ float g_G[16 * HH];
__device__ float g_c[HH];

// ---------------- setup kernels (replace memset/memcpy: pure kernel graph) ----------------
// zero g_deg, g_esum, g_EA, g_EB
__global__ void zero_kernel() {
    int i = blockIdx.x * blockDim.x + threadIdx.x;
    if (i < NN) g_deg[i] = 0;
    if (i < NN * 16) g_esum[i] = 0.f;
    if (i < NN * HH) { g_EA[i] = 0.f; g_EB[i] = 0.f; }
}

__global__ void init_small_kernel(const float* __restrict__ eeW, const float* __restrict__ eeb) {
    int t = blockIdx.x * blockDim.x + threadIdx.x;
    if (t < 16 * HH) g_EW[t] = eeW[t];
    if (t < HH) g_ec[t] = eeb[t];
}

__global__ void cursor_copy_kernel() {
    int i = blockIdx.x * blockDim.x + threadIdx.x;
    if (i < NN) g_cursor[i] = g_rowptr[i];
}

__global__ void out_kernel(float* __restrict__ out) {
    int i = blockIdx.x * blockDim.x + threadIdx.x;
    if (i < NN * HH) {
        out[i] = g_h[i];
        out[NN * HH + i] = g_p[i];
    }
}

// ---------------- CSR build ----------------
__global__ void deg_kernel(const int* __restrict__ rec) {
    int j = blockIdx.x * blockDim.x + threadIdx.x;
    if (j < EE) atomicAdd(&g_deg[rec[j]], 1);
}

__global__ void esum_kernel(const int* __restrict__ rec, const float* __restrict__ e_in) {
    int g = blockIdx.x * blockDim.x + threadIdx.x;
    if (g >= EE * 16) return;
    int j = g >> 4, k = g & 15;
    atomicAdd(&g_esum[rec[j] * 16 + k], e_in[g]);
}

__global__ __launch_bounds__(1024) void scan_kernel(int n) {
    __shared__ int wsum[32];
    __shared__ int carry;
    int t = threadIdx.x, lane = t & 31, wid = t >> 5;
    if (t == 0) { carry = 0; g_rowptr[0] = 0; }
    __syncthreads();
    for (int base = 0; base < n; base += 1024) {
        int i = base + t;
        int v = (i < n) ? g_deg[i] : 0;
        int x = v;
        #pragma unroll
        for (int o = 1; o < 32; o <<= 1) {
            int y = __shfl_up_sync(0xffffffffu, x, o);
            if (lane >= o) x += y;
        }
        if (lane == 31) wsum[wid] = x;
        __syncthreads();
        if (wid == 0) {
            int s = wsum[lane];
            #pragma unroll
            for (int o = 1; o < 32; o <<= 1) {
                int y = __shfl_up_sync(0xffffffffu, s, o);
                if (lane >= o) s += y;
            }
            wsum[lane] = s;
        }
        __syncthreads();
        int off = carry + (wid ? wsum[wid - 1] : 0);
        if (i < n) g_rowptr[i + 1] = off + x;
        __syncthreads();
        if (t == 0) carry += wsum[31];
        __syncthreads();
    }
}

__global__ void fill_kernel(const int* __restrict__ send, const int* __restrict__ rec) {
    int j = blockIdx.x * blockDim.x + threadIdx.x;
    if (j < EE) {
        int pos = atomicAdd(&g_cursor[rec[j]], 1);
        g_col[pos] = send[j];
    }
}

// ---------------- node GEMM: C[N,64] = bias + sum_t A_t[N,Kt] @ W_t[Kt,64] ----------------
__global__ __launch_bounds__(256) void node_gemm(
    float* __restrict__ C,
    const float* __restrict__ A0, const float* __restrict__ W0, int K0,
    const float* __restrict__ A1, const float* __restrict__ W1, int K1,
    const float* __restrict__ A2, const float* __restrict__ W2, int K2,
    const float* __restrict__ bias, int N)
{
    __shared__ float As[16][64];      // [k][row]
    __shared__ float Ws[16][68];      // [k][col], padded
    int r0 = blockIdx.x * 64;
    int t = threadIdx.x;
    int tx = t & 15, ty = t >> 4;     // 16 x 16 thread grid
    float acc[4][4] = {};

    #pragma unroll 1
    for (int term = 0; term < 3; term++) {
        const float* A; const float* W; int K;
        if (term == 0) { A = A0; W = W0; K = K0; }
        else if (term == 1) { A = A1; W = W1; K = K1; }
        else { A = A2; W = W2; K = K2; }
        if (A == nullptr) continue;
        for (int k0 = 0; k0 < K; k0 += 16) {
            __syncthreads();
            #pragma unroll
            for (int pp = 0; pp < 4; pp++) {
                int idx = t + 256 * pp;
                int rr = idx >> 4, kk = idx & 15;
                int gr = r0 + rr;
                As[kk][rr] = (gr < N) ? A[gr * K + k0 + kk] : 0.f;
            }
            #pragma unroll
            for (int pp = 0; pp < 4; pp++) {
                int idx = t + 256 * pp;
                int kk = idx >> 6, cc = idx & 63;
                Ws[kk][cc] = W[(k0 + kk) * 64 + cc];
            }
            __syncthreads();
            #pragma unroll
            for (int kk = 0; kk < 16; kk++) {
                float a[4], w[4];
                #pragma unroll
                for (int i = 0; i < 4; i++) a[i] = As[kk][ty * 4 + i];
                #pragma unroll
                for (int j = 0; j < 4; j++) w[j] = Ws[kk][tx * 4 + j];
                #pragma unroll
                for (int i = 0; i < 4; i++)
                    #pragma unroll
                    for (int j = 0; j < 4; j++)
                        acc[i][j] += a[i] * w[j];
            }
        }
    }

    #pragma unroll
    for (int i = 0; i < 4; i++) {
        int gr = r0 + ty * 4 + i;
        if (gr < N) {
            float4 v;
            float b0 = bias ? bias[tx * 4 + 0] : 0.f;
            float b1 = bias ? bias[tx * 4 + 1] : 0.f;
            float b2 = bias ? bias[tx * 4 + 2] : 0.f;
            float b3 = bias ? bias[tx * 4 + 3] : 0.f;
            v.x = acc[i][0] + b0; v.y = acc[i][1] + b1;
            v.z = acc[i][2] + b2; v.w = acc[i][3] + b3;
            *(float4*)&C[gr * 64 + tx * 4] = v;
        }
    }
}

// ---------------- SpMM + extras: agg[n] = sum_{j:rec=n} S[send_j] + esum[n]@G + deg[n]*(R[n]+c) ----
__global__ __launch_bounds__(256) void spmm_kernel(
    float* __restrict__ agg, const float* __restrict__ S, const float* __restrict__ R, int n)
{
    __shared__ float sG[16 * 64];
    __shared__ float sc[64];
    int t = threadIdx.x;
    for (int i = t; i < 1024; i += 256) sG[i] = g_G[i];
    if (t < 64) sc[t] = g_c[t];
    __syncthreads();
    int node = blockIdx.x * 8 + (t >> 5);
    if (node >= n) return;
    int lane = t & 31;
    int beg = g_rowptr[node], end = g_rowptr[node + 1];
    const float2* S2 = (const float2*)S;
    float ax = 0.f, ay = 0.f, bx = 0.f, by = 0.f;
    int e = beg;
    for (; e + 4 <= end; e += 4) {
        int u0 = g_col[e], u1 = g_col[e + 1], u2 = g_col[e + 2], u3 = g_col[e + 3];
        float2 v0 = S2[u0 * 32 + lane];
        float2 v1 = S2[u1 * 32 + lane];
        float2 v2 = S2[u2 * 32 + lane];
        float2 v3 = S2[u3 * 32 + lane];
        ax += v0.x + v2.x; ay += v0.y + v2.y;
        bx += v1.x + v3.x; by += v1.y + v3.y;
    }
    for (; e < end; e++) {
        int u = g_col[e];
        float2 v = S2[u * 32 + lane];
        ax += v.x; ay += v.y;
    }
    float deg = (float)(end - beg);
    int c0 = lane * 2;
    float2 r2 = ((const float2*)R)[node * 32 + lane];
    float t0 = deg * (r2.x + sc[c0]) + ax + bx;
    float t1 = deg * (r2.y + sc[c0 + 1]) + ay + by;
    #pragma unroll
    for (int k = 0; k < 16; k++) {
        float ev = g_esum[node * 16 + k];
        t0 += ev * sG[k * 64 + c0];
        t1 += ev * sG[k * 64 + c0 + 1];
    }
    ((float2*)agg)[node * 32 + lane] = make_float2(t0, t1);
}

// ---------------- small matrix kernels ----------------
// G = EW @ We (16x64 @ 64x64), c = b + ec @ We
__global__ __launch_bounds__(1024) void small_h_kernel(const float* __restrict__ We,
                                                       const float* __restrict__ b)
{
    int t = threadIdx.x;
    int r = t >> 6, c = t & 63;
    float s = 0.f;
    #pragma unroll
    for (int k = 0; k < 64; k++) s += g_EW[r * 64 + k] * We[k * 64 + c];
    g_G[t] = s;
    if (t < 64) {
        float s2 = b[t];
        #pragma unroll
        for (int k = 0; k < 64; k++) s2 += g_ec[k] * We[k * 64 + t];
        g_c[t] = s2;
    }
}

// EW <- EW @ We_e ; ec <- eu_b + ec @ We_e ; then G = EW_new @ Wp_e, c = pm_b + ec_new @ Wp_e
__global__ __launch_bounds__(1024) void small_p_kernel(const float* __restrict__ WeE,
                                                       const float* __restrict__ eb,
                                                       const float* __restrict__ WpE,
                                                       const float* __restrict__ pb)
{
    __shared__ float sEW[1024], sec[64], sEWn[1024], secn[64];
    int t = threadIdx.x;
    sEW[t] = g_EW[t];
    if (t < 64) sec[t] = g_ec[t];
    __syncthreads();
    int r = t >> 6, c = t & 63;
    float s = 0.f;
    #pragma unroll
    for (int k = 0; k < 64; k++) s += sEW[r * 64 + k] * WeE[k * 64 + c];
    sEWn[t] = s; g_EW[t] = s;
    if (t < 64) {
        float s2 = eb[t];
        #pragma unroll
        for (int k = 0; k < 64; k++) s2 += sec[k] * WeE[k * 64 + t];
        secn[t] = s2; g_ec[t] = s2;
    }
    __syncthreads();
    float gg = 0.f;
    #pragma unroll
    for (int k = 0; k < 64; k++) gg += sEWn[r * 64 + k] * WpE[k * 64 + c];
    g_G[t] = gg;
    if (t < 64) {
        float s3 = pb[t];
        #pragma unroll
        for (int k = 0; k < 64; k++) s3 += secn[k] * WpE[k * 64 + t];
        g_c[t] = s3;
    }
}

// ---------------- device pointer helper kernels need raw addresses for GEMMs ----------------
// We get scratch addresses host-side once via cudaGetSymbolAddress OUTSIDE capture is not
// possible (kernel_launch is the only entry point), but cudaGetSymbolAddress is a pure
// driver query (no stream ops, no allocation) and is capture-safe. Still, to keep the
// captured graph 100% kernel-only, all data movement above is done by kernels; only
// address queries remain here.

extern "C" void kernel_launch(void* const* d_in, const int* in_sizes, int n_in,
                              void* d_out, int out_size)
{
    const float* h_in = (const float*)d_in[0];
    const float* e_in = (const float*)d_in[1];
    const float* p_in = (const float*)d_in[2];
    const int*   ei   = (const int*)d_in[3];
    const int* send = ei;
    const int* rec  = ei + EE;
    const float* he_W = (const float*)d_in[4];
    const float* he_b = (const float*)d_in[5];
    const float* ee_W = (const float*)d_in[6];
    const float* ee_b = (const float*)d_in[7];
    const float* pe_W = (const float*)d_in[8];
    const float* pe_b = (const float*)d_in[9];
    const float* hm_W = (const float*)d_in[10];
    const float* hm_b = (const float*)d_in[11];
    const float* hu_W = (const float*)d_in[12];
    const float* hu_b = (const float*)d_in[13];
    const float* eu_W = (const float*)d_in[14];
    const float* eu_b = (const float*)d_in[15];
    const float* pm_W = (const float*)d_in[16];
    const float* pm_b = (const float*)d_in[17];
    const float* pu_W = (const float*)d_in[18];
    const float* pu_b = (const float*)d_in[19];

    static float* fh = nullptr;
    static float *fp, *fEA, *fEB, *fS, *fR, *fagg;
    if (fh == nullptr) {
        void* ptr;
        cudaGetSymbolAddress(&ptr, g_h);   fh   = (float*)ptr;
        cudaGetSymbolAddress(&ptr, g_p);   fp   = (float*)ptr;
        cudaGetSymbolAddress(&ptr, g_EA);  fEA  = (float*)ptr;
        cudaGetSymbolAddress(&ptr, g_EB);  fEB  = (float*)ptr;
        cudaGetSymbolAddress(&ptr, g_S);   fS   = (float*)ptr;
        cudaGetSymbolAddress(&ptr, g_R);   fR   = (float*)ptr;
        cudaGetSymbolAddress(&ptr, g_agg); fagg = (float*)ptr;
    }

    const int GB = (NN + 63) / 64;   // node gemm blocks
    const int EB256 = (EE + 255) / 256;
    const int ZB = (NN * HH + 255) / 256;

    // ----- setup (kernel-only graph) -----
    zero_kernel<<<ZB, 256>>>();
    init_small_kernel<<<(16 * HH + 255) / 256, 256>>>(ee_W, ee_b);

    deg_kernel<<<EB256, 256>>>(rec);
    esum_kernel<<<(EE * 16 + 255) / 256, 256>>>(rec, e_in);
    scan_kernel<<<1, 1024>>>(NN);
    cursor_copy_kernel<<<(NN + 255) / 256, 256>>>();
    fill_kernel<<<EB256, 256>>>(send, rec);

    // ----- embeddings -----
    node_gemm<<<GB, 256>>>(fh, h_in, he_W, 128,
                           nullptr, nullptr, 0, nullptr, nullptr, 0, he_b, NN);
    node_gemm<<<GB, 256>>>(fp, p_in, pe_W, 16,
                           nullptr, nullptr, 0, nullptr, nullptr, 0, pe_b, NN);

    // ----- layers -----
    for (int i = 0; i < 4; i++) {
        const float* hmW = hm_W + (size_t)i * 320 * 64;
        const float* huW = hu_W + (size_t)i * 128 * 64;
        const float* euW = eu_W + (size_t)i * 192 * 64;
        const float* pmW = pm_W + (size_t)i * 192 * 64;
        const float* puW = pu_W + (size_t)i * 128 * 64;
        const float* Wm_hs = hmW;
        const float* Wm_ps = hmW + 64 * 64;
        const float* Wm_hr = hmW + 128 * 64;
        const float* Wm_pr = hmW + 192 * 64;
        const float* Wm_e  = hmW + 256 * 64;
        const float* We_hs = euW;
        const float* We_hr = euW + 64 * 64;
        const float* We_e  = euW + 128 * 64;
        const float* Wp_ps = pmW;
        const float* Wp_pr = pmW + 64 * 64;
        const float* Wp_e  = pmW + 128 * 64;

        // h branch
        small_h_kernel<<<1, 1024>>>(Wm_e, hm_b + i * 64);
        node_gemm<<<GB, 256>>>(fS, fh, Wm_hs, 64, fp, Wm_ps, 64, fEA, Wm_e, 64, nullptr, NN);
        node_gemm<<<GB, 256>>>(fR, fh, Wm_hr, 64, fp, Wm_pr, 64, fEB, Wm_e, 64, nullptr, NN);
        spmm_kernel<<<(NN + 7) / 8, 256>>>(fagg, fS, fR, NN);
        node_gemm<<<GB, 256>>>(fh, fh, huW, 64, fagg, huW + 64 * 64, 64,
                               nullptr, nullptr, 0, hu_b + i * 64, NN);

        // e branch (symbolic): EA' = h@We_hs + EA@We_e ; EB' = h@We_hr + EB@We_e
        node_gemm<<<GB, 256>>>(fEA, fh, We_hs, 64, fEA, We_e, 64,
                               nullptr, nullptr, 0, nullptr, NN);
        node_gemm<<<GB, 256>>>(fEB, fh, We_hr, 64, fEB, We_e, 64,
                               nullptr, nullptr, 0, nullptr, NN);
        small_p_kernel<<<1, 1024>>>(We_e, eu_b + i * 64, Wp_e, pm_b + i * 64);

        // p branch
        node_gemm<<<GB, 256>>>(fS, fp, Wp_ps, 64, fEA, Wp_e, 64,
                               nullptr, nullptr, 0, nullptr, NN);
        node_gemm<<<GB, 256>>>(fR, fp, Wp_pr, 64, fEB, Wp_e, 64,
                               nullptr, nullptr, 0, nullptr, NN);
        spmm_kernel<<<(NN + 7) / 8, 256>>>(fagg, fS, fR, NN);
        node_gemm<<<GB, 256>>>(fp, fp, puW, 64, fagg, puW + 64 * 64, 64,
                               nullptr, nullptr, 0, pu_b + i * 64, NN);
    }

    // ----- output: (h, p) concatenated -----
    out_kernel<<<ZB, 256>>>((float*)d_out);
}

// round 6
// speedup vs baseline: 1.5708x; 1.5708x over previous
#include <cuda_runtime.h>
#include <cuda_bf16.h>

#define NN 50000
#define EE 800000
#define HH 64
#define LL 4

// ---------------- device scratch (no allocs allowed) ----------------
__device__ float g_h[NN * HH];
__device__ float g_p[NN * HH];
__device__ float g_EA[NN * HH];
__device__ float g_EB[NN * HH];
__device__ float g_S[NN * HH];
__device__ float g_R[NN * HH];
__device__ float g_agg[NN * HH];
__device__ float g_esum[NN * 16];
__device__ int   g_deg[NN];
__device__ int   g_rowptr[NN + 1];
__device__ int   g_cursor[NN];
__device__ int   g_col[EE];
// precomputed per-layer small matrices
__device__ float g_Gh[LL * 16 * HH];
__device__ float g_ch[LL * HH];
__device__ float g_Gp[LL * 16 * HH];
__device__ float g_cp[LL * HH];

// ---------------- setup kernels ----------------
__global__ void zero_kernel() {
    int i = blockIdx.x * blockDim.x + threadIdx.x;
    if (i < NN) g_deg[i] = 0;
    if (i < NN * 16) g_esum[i] = 0.f;
}

__global__ void cursor_copy_kernel() {
    int i = blockIdx.x * blockDim.x + threadIdx.x;
    if (i < NN) g_cursor[i] = g_rowptr[i];
}

__global__ void out_kernel(float* __restrict__ out) {
    int i = blockIdx.x * blockDim.x + threadIdx.x;
    if (i < NN * HH) {
        out[i] = g_h[i];
        out[NN * HH + i] = g_p[i];
    }
}

// ---------------- CSR build ----------------
__global__ void deg_kernel(const int* __restrict__ rec) {
    int j = blockIdx.x * blockDim.x + threadIdx.x;
    if (j < EE) atomicAdd(&g_deg[rec[j]], 1);
}

__global__ void esum_kernel(const int* __restrict__ rec, const float* __restrict__ e_in) {
    int g = blockIdx.x * blockDim.x + threadIdx.x;
    if (g >= EE * 16) return;
    int j = g >> 4, k = g & 15;
    atomicAdd(&g_esum[rec[j] * 16 + k], e_in[g]);
}

__global__ __launch_bounds__(1024) void scan_kernel(int n) {
    __shared__ int wsum[32];
    __shared__ int carry;
    int t = threadIdx.x, lane = t & 31, wid = t >> 5;
    if (t == 0) { carry = 0; g_rowptr[0] = 0; }
    __syncthreads();
    for (int base = 0; base < n; base += 1024) {
        int i = base + t;
        int v = (i < n) ? g_deg[i] : 0;
        int x = v;
        #pragma unroll
        for (int o = 1; o < 32; o <<= 1) {
            int y = __shfl_up_sync(0xffffffffu, x, o);
            if (lane >= o) x += y;
        }
        if (lane == 31) wsum[wid] = x;
        __syncthreads();
        if (wid == 0) {
            int s = wsum[lane];
            #pragma unroll
            for (int o = 1; o < 32; o <<= 1) {
                int y = __shfl_up_sync(0xffffffffu, s, o);
                if (lane >= o) s += y;
            }
            wsum[lane] = s;
        }
        __syncthreads();
        int off = carry + (wid ? wsum[wid - 1] : 0);
        if (i < n) g_rowptr[i + 1] = off + x;
        __syncthreads();
        if (t == 0) carry += wsum[31];
        __syncthreads();
    }
}

__global__ void fill_kernel(const int* __restrict__ send, const int* __restrict__ rec) {
    int j = blockIdx.x * blockDim.x + threadIdx.x;
    if (j < EE) {
        int pos = atomicAdd(&g_cursor[rec[j]], 1);
        g_col[pos] = send[j];
    }
}

// ---------------- precompute all layer small matrices in one launch ----------------
// EW_0 = ee_W (16x64), ec_0 = ee_b.
// Layer i: Gh_i = EW_i @ Wm_e_i ; ch_i = hm_b_i + ec_i @ Wm_e_i
//          EW_{i+1} = EW_i @ We_e_i ; ec_{i+1} = eu_b_i + ec_i @ We_e_i
//          Gp_i = EW_{i+1} @ Wp_e_i ; cp_i = pm_b_i + ec_{i+1} @ Wp_e_i
__global__ __launch_bounds__(1024) void precompute_small(
    const float* __restrict__ eeW, const float* __restrict__ eeb,
    const float* __restrict__ hmW, const float* __restrict__ hmb,
    const float* __restrict__ euW, const float* __restrict__ eub,
    const float* __restrict__ pmW, const float* __restrict__ pmb)
{
    __shared__ float sEW[1024], sec[64], sEW2[1024], sec2[64];
    int t = threadIdx.x;
    int r = t >> 6, c = t & 63;
    sEW[t] = eeW[t];
    if (t < 64) sec[t] = eeb[t];
    __syncthreads();
    for (int i = 0; i < LL; i++) {
        const float* Wm_e = hmW + (size_t)i * 320 * 64 + 256 * 64;
        const float* We_e = euW + (size_t)i * 192 * 64 + 128 * 64;
        const float* Wp_e = pmW + (size_t)i * 192 * 64 + 128 * 64;
        float s = 0.f;
        #pragma unroll 8
        for (int k = 0; k < 64; k++) s += sEW[r * 64 + k] * Wm_e[k * 64 + c];
        g_Gh[i * 1024 + t] = s;
        if (t < 64) {
            float s2 = hmb[i * 64 + t];
            for (int k = 0; k < 64; k++) s2 += sec[k] * Wm_e[k * 64 + t];
            g_ch[i * 64 + t] = s2;
        }
        s = 0.f;
        #pragma unroll 8
        for (int k = 0; k < 64; k++) s += sEW[r * 64 + k] * We_e[k * 64 + c];
        sEW2[t] = s;
        if (t < 64) {
            float s2 = eub[i * 64 + t];
            for (int k = 0; k < 64; k++) s2 += sec[k] * We_e[k * 64 + t];
            sec2[t] = s2;
        }
        __syncthreads();
        sEW[t] = sEW2[t];
        if (t < 64) sec[t] = sec2[t];
        __syncthreads();
        s = 0.f;
        #pragma unroll 8
        for (int k = 0; k < 64; k++) s += sEW[r * 64 + k] * Wp_e[k * 64 + c];
        g_Gp[i * 1024 + t] = s;
        if (t < 64) {
            float s2 = pmb[i * 64 + t];
            for (int k = 0; k < 64; k++) s2 += sec[k] * Wp_e[k * 64 + t];
            g_cp[i * 64 + t] = s2;
        }
        __syncthreads();
    }
}

// ---------------- tensor-core node GEMM ----------------
// C[N,64] = bias + sum_t A_t[N,Kt] @ W_t[Kt,64]
// fp32 emulated via bf16 hi/lo split: A*W ~= Ah*Wh + Ah*Wl + Al*Wh  (err ~2^-16)
// mma.sync.m16n8k16 bf16. BM=128 rows/block, 256 threads = 8 warps (4x2 warp grid).

__device__ __forceinline__ void mma_bf16(float* d, const unsigned* a, const unsigned* b) {
    asm volatile(
        "mma.sync.aligned.m16n8k16.row.col.f32.bf16.bf16.f32 "
        "{%0,%1,%2,%3}, {%4,%5,%6,%7}, {%8,%9}, {%0,%1,%2,%3};"
        : "+f"(d[0]), "+f"(d[1]), "+f"(d[2]), "+f"(d[3])
        : "r"(a[0]), "r"(a[1]), "r"(a[2]), "r"(a[3]), "r"(b[0]), "r"(b[1]));
}

__device__ __forceinline__ void split2(float x, float y, unsigned& hi, unsigned& lo) {
    // pack (x,y) -> bf16x2 hi (x in low half), and residual lo
    __nv_bfloat16 hx = __float2bfloat16_rn(x);
    __nv_bfloat16 hy = __float2bfloat16_rn(y);
    __nv_bfloat162 hp; hp.x = hx; hp.y = hy;
    hi = *(unsigned*)&hp;
    float lx = x - __bfloat162float(hx);
    float ly = y - __bfloat162float(hy);
    __nv_bfloat162 lp = __floats2bfloat162_rn(lx, ly);
    lo = *(unsigned*)&lp;
}

__global__ __launch_bounds__(256) void mma_gemm(
    float* __restrict__ C,
    const float* __restrict__ A0, const float* __restrict__ W0, int K0,
    const float* __restrict__ A1, const float* __restrict__ W1, int K1,
    const float* __restrict__ A2, const float* __restrict__ W2, int K2,
    const float* __restrict__ bias, int N)
{
    // shared: A tile hi/lo as u32 pairs [128 rows][12 words] (8 used, stride 12 kills conflicts)
    //         W tile transposed hi/lo bf16 [64 cols][24 halves] (16 used)
    __shared__ unsigned sAh[128 * 12];
    __shared__ unsigned sAl[128 * 12];
    __shared__ unsigned sWh[64 * 12];
    __shared__ unsigned sWl[64 * 12];

    int r0 = blockIdx.x * 128;
    int t = threadIdx.x;
    int w = t >> 5, lane = t & 31;
    int wm = w >> 1, wn = w & 1;     // 4 x 2 warps
    int gq = lane >> 2, q = lane & 3;

    float d[2][4][4];
    #pragma unroll
    for (int mt = 0; mt < 2; mt++)
        #pragma unroll
        for (int nt = 0; nt < 4; nt++)
            #pragma unroll
            for (int i = 0; i < 4; i++) d[mt][nt][i] = 0.f;

    int s_row = t >> 1;              // staging: row 0..127
    int s_kh  = t & 1;               // k-half (0: k0..7, 1: k8..15)
    int s_wk  = t >> 4;              // W staging: k 0..15
    int s_wc  = (t & 15) * 4;        // W staging: col base

    #pragma unroll 1
    for (int term = 0; term < 3; term++) {
        const float* A; const float* W; int K;
        if (term == 0) { A = A0; W = W0; K = K0; }
        else if (term == 1) { A = A1; W = W1; K = K1; }
        else { A = A2; W = W2; K = K2; }
        if (A == nullptr) continue;

        #pragma unroll 1
        for (int k0 = 0; k0 < K; k0 += 16) {
            __syncthreads();
            // ---- stage A: 128 x 16 fp32 -> hi/lo bf16 pairs ----
            {
                int gr = r0 + s_row;
                float v[8];
                if (gr < N) {
                    const float* ap = A + (size_t)gr * K + k0 + s_kh * 8;
                    float4 x = *(const float4*)ap;
                    float4 y = *(const float4*)(ap + 4);
                    v[0]=x.x; v[1]=x.y; v[2]=x.z; v[3]=x.w;
                    v[4]=y.x; v[5]=y.y; v[6]=y.z; v[7]=y.w;
                } else {
                    #pragma unroll
                    for (int i = 0; i < 8; i++) v[i] = 0.f;
                }
                #pragma unroll
                for (int i = 0; i < 4; i++) {
                    unsigned hi, lo;
                    split2(v[2*i], v[2*i+1], hi, lo);
                    sAh[s_row * 12 + s_kh * 4 + i] = hi;
                    sAl[s_row * 12 + s_kh * 4 + i] = lo;
                }
            }
            // ---- stage W: 16 x 64 fp32 -> transposed hi/lo bf16 [col][k] ----
            {
                const float* wp = W + (size_t)(k0 + s_wk) * 64 + s_wc;
                float4 x = *(const float4*)wp;
                float vv[4] = {x.x, x.y, x.z, x.w};
                __nv_bfloat16* wh = (__nv_bfloat16*)sWh;
                __nv_bfloat16* wl = (__nv_bfloat16*)sWl;
                #pragma unroll
                for (int i = 0; i < 4; i++) {
                    __nv_bfloat16 hb = __float2bfloat16_rn(vv[i]);
                    float lf = vv[i] - __bfloat162float(hb);
                    wh[(s_wc + i) * 24 + s_wk] = hb;
                    wl[(s_wc + i) * 24 + s_wk] = __float2bfloat16_rn(lf);
                }
            }
            __syncthreads();

            // ---- fragments ----
            unsigned ah[2][4], al[2][4];
            #pragma unroll
            for (int mt = 0; mt < 2; mt++) {
                int r = wm * 32 + mt * 16 + gq;
                ah[mt][0] = sAh[r * 12 + q];
                ah[mt][1] = sAh[(r + 8) * 12 + q];
                ah[mt][2] = sAh[r * 12 + q + 4];
                ah[mt][3] = sAh[(r + 8) * 12 + q + 4];
                al[mt][0] = sAl[r * 12 + q];
                al[mt][1] = sAl[(r + 8) * 12 + q];
                al[mt][2] = sAl[r * 12 + q + 4];
                al[mt][3] = sAl[(r + 8) * 12 + q + 4];
            }
            unsigned bh[4][2], bl[4][2];
            #pragma unroll
            for (int nt = 0; nt < 4; nt++) {
                int c = wn * 32 + nt * 8 + gq;
                bh[nt][0] = sWh[c * 12 + q];
                bh[nt][1] = sWh[c * 12 + q + 4];
                bl[nt][0] = sWl[c * 12 + q];
                bl[nt][1] = sWl[c * 12 + q + 4];
            }
            #pragma unroll
            for (int mt = 0; mt < 2; mt++)
                #pragma unroll
                for (int nt = 0; nt < 4; nt++) {
                    mma_bf16(d[mt][nt], ah[mt], bh[nt]);
                    mma_bf16(d[mt][nt], ah[mt], bl[nt]);
                    mma_bf16(d[mt][nt], al[mt], bh[nt]);
                }
        }
    }

    // ---- epilogue ----
    #pragma unroll
    for (int nt = 0; nt < 4; nt++) {
        int col = wn * 32 + nt * 8 + q * 2;
        float bx = bias ? bias[col] : 0.f;
        float by = bias ? bias[col + 1] : 0.f;
        #pragma unroll
        for (int mt = 0; mt < 2; mt++) {
            int row = r0 + wm * 32 + mt * 16 + gq;
            if (row < N)
                *(float2*)&C[(size_t)row * 64 + col] =
                    make_float2(d[mt][nt][0] + bx, d[mt][nt][1] + by);
            if (row + 8 < N)
                *(float2*)&C[(size_t)(row + 8) * 64 + col] =
                    make_float2(d[mt][nt][2] + bx, d[mt][nt][3] + by);
        }
    }
}

// ---------------- SpMM: agg[n] = sum_{j:rec=n} S[send_j] + esum[n]@G + deg[n]*(R[n]+c) ----
__global__ __launch_bounds__(256) void spmm_kernel(
    float* __restrict__ agg, const float* __restrict__ S, const float* __restrict__ R,
    int layer, int pbranch, int n)
{
    __shared__ float sG[16 * 64];
    __shared__ float sc[64];
    int t = threadIdx.x;
    const float* G = (pbranch ? g_Gp : g_Gh) + layer * 1024;
    const float* c = (pbranch ? g_cp : g_ch) + layer * 64;
    for (int i = t; i < 1024; i += 256) sG[i] = G[i];
    if (t < 64) sc[t] = c[t];
    __syncthreads();
    int node = blockIdx.x * 8 + (t >> 5);
    if (node >= n) return;
    int lane = t & 31;
    int beg = g_rowptr[node], end = g_rowptr[node + 1];
    const float2* S2 = (const float2*)S;
    float ax = 0.f, ay = 0.f, bx = 0.f, by = 0.f;
    int e = beg;
    for (; e + 4 <= end; e += 4) {
        int u0 = g_col[e], u1 = g_col[e + 1], u2 = g_col[e + 2], u3 = g_col[e + 3];
        float2 v0 = S2[u0 * 32 + lane];
        float2 v1 = S2[u1 * 32 + lane];
        float2 v2 = S2[u2 * 32 + lane];
        float2 v3 = S2[u3 * 32 + lane];
        ax += v0.x + v2.x; ay += v0.y + v2.y;
        bx += v1.x + v3.x; by += v1.y + v3.y;
    }
    for (; e < end; e++) {
        int u = g_col[e];
        float2 v = S2[u * 32 + lane];
        ax += v.x; ay += v.y;
    }
    float deg = (float)(end - beg);
    int c0 = lane * 2;
    float2 r2 = ((const float2*)R)[node * 32 + lane];
    float t0 = deg * (r2.x + sc[c0]) + ax + bx;
    float t1 = deg * (r2.y + sc[c0 + 1]) + ay + by;
    #pragma unroll
    for (int k = 0; k < 16; k++) {
        float ev = g_esum[node * 16 + k];
        t0 += ev * sG[k * 64 + c0];
        t1 += ev * sG[k * 64 + c0 + 1];
    }
    ((float2*)agg)[node * 32 + lane] = make_float2(t0, t1);
}

// ---------------- host ----------------
extern "C" void kernel_launch(void* const* d_in, const int* in_sizes, int n_in,
                              void* d_out, int out_size)
{
    const float* h_in = (const float*)d_in[0];
    const float* e_in = (const float*)d_in[1];
    const float* p_in = (const float*)d_in[2];
    const int*   ei   = (const int*)d_in[3];
    const int* send = ei;
    const int* rec  = ei + EE;
    const float* he_W = (const float*)d_in[4];
    const float* he_b = (const float*)d_in[5];
    const float* ee_W = (const float*)d_in[6];
    const float* ee_b = (const float*)d_in[7];
    const float* pe_W = (const float*)d_in[8];
    const float* pe_b = (const float*)d_in[9];
    const float* hm_W = (const float*)d_in[10];
    const float* hm_b = (const float*)d_in[11];
    const float* hu_W = (const float*)d_in[12];
    const float* hu_b = (const float*)d_in[13];
    const float* eu_W = (const float*)d_in[14];
    const float* eu_b = (const float*)d_in[15];
    const float* pm_W = (const float*)d_in[16];
    const float* pm_b = (const float*)d_in[17];
    const float* pu_W = (const float*)d_in[18];
    const float* pu_b = (const float*)d_in[19];

    static float* fh = nullptr;
    static float *fp, *fEA, *fEB, *fS, *fR, *fagg;
    if (fh == nullptr) {
        void* ptr;
        cudaGetSymbolAddress(&ptr, g_h);   fh   = (float*)ptr;
        cudaGetSymbolAddress(&ptr, g_p);   fp   = (float*)ptr;
        cudaGetSymbolAddress(&ptr, g_EA);  fEA  = (float*)ptr;
        cudaGetSymbolAddress(&ptr, g_EB);  fEB  = (float*)ptr;
        cudaGetSymbolAddress(&ptr, g_S);   fS   = (float*)ptr;
        cudaGetSymbolAddress(&ptr, g_R);   fR   = (float*)ptr;
        cudaGetSymbolAddress(&ptr, g_agg); fagg = (float*)ptr;
    }

    const int GB = (NN + 127) / 128;     // mma gemm blocks
    const int EB256 = (EE + 255) / 256;
    const int ZB = (NN * HH + 255) / 256;
    const int SB = (NN + 7) / 8;

    // ----- setup -----
    zero_kernel<<<(NN * 16 + 255) / 256, 256>>>();
    precompute_small<<<1, 1024>>>(ee_W, ee_b, hm_W, hm_b, eu_W, eu_b, pm_W, pm_b);

    deg_kernel<<<EB256, 256>>>(rec);
    esum_kernel<<<(EE * 16 + 255) / 256, 256>>>(rec, e_in);
    scan_kernel<<<1, 1024>>>(NN);
    cursor_copy_kernel<<<(NN + 255) / 256, 256>>>();
    fill_kernel<<<EB256, 256>>>(send, rec);

    // ----- embeddings -----
    mma_gemm<<<GB, 256>>>(fh, h_in, he_W, 128,
                          nullptr, nullptr, 0, nullptr, nullptr, 0, he_b, NN);
    mma_gemm<<<GB, 256>>>(fp, p_in, pe_W, 16,
                          nullptr, nullptr, 0, nullptr, nullptr, 0, pe_b, NN);

    // ----- layers -----
    for (int i = 0; i < LL; i++) {
        const float* hmW = hm_W + (size_t)i * 320 * 64;
        const float* huW = hu_W + (size_t)i * 128 * 64;
        const float* euW = eu_W + (size_t)i * 192 * 64;
        const float* pmW = pm_W + (size_t)i * 192 * 64;
        const float* puW = pu_W + (size_t)i * 128 * 64;
        const float* Wm_hs = hmW;
        const float* Wm_ps = hmW + 64 * 64;
        const float* Wm_hr = hmW + 128 * 64;
        const float* Wm_pr = hmW + 192 * 64;
        const float* Wm_e  = hmW + 256 * 64;
        const float* We_hs = euW;
        const float* We_hr = euW + 64 * 64;
        const float* We_e  = euW + 128 * 64;
        const float* Wp_ps = pmW;
        const float* Wp_pr = pmW + 64 * 64;
        const float* Wp_e  = pmW + 128 * 64;

        // layer 0: EA = EB = 0 symbolically -> drop those terms entirely
        const float* tEA = (i == 0) ? nullptr : fEA;
        const float* tEB = (i == 0) ? nullptr : fEB;

        // h branch
        mma_gemm<<<GB, 256>>>(fS, fh, Wm_hs, 64, fp, Wm_ps, 64,
                              tEA, Wm_e, 64, nullptr, NN);
        mma_gemm<<<GB, 256>>>(fR, fh, Wm_hr, 64, fp, Wm_pr, 64,
                              tEB, Wm_e, 64, nullptr, NN);
        spmm_kernel<<<SB, 256>>>(fagg, fS, fR, i, 0, NN);
        mma_gemm<<<GB, 256>>>(fh, fh, huW, 64, fagg, huW + 64 * 64, 64,
                              nullptr, nullptr, 0, hu_b + i * 64, NN);

        // e branch (symbolic): EA' = h@We_hs + EA@We_e ; EB' = h@We_hr + EB@We_e
        mma_gemm<<<GB, 256>>>(fEA, fh, We_hs, 64, tEA, We_e, 64,
                              nullptr, nullptr, 0, nullptr, NN);
        mma_gemm<<<GB, 256>>>(fEB, fh, We_hr, 64, tEB, We_e, 64,
                              nullptr, nullptr, 0, nullptr, NN);

        // p branch
        mma_gemm<<<GB, 256>>>(fS, fp, Wp_ps, 64, fEA, Wp_e, 64,
                              nullptr, nullptr, 0, nullptr, NN);
        mma_gemm<<<GB, 256>>>(fR, fp, Wp_pr, 64, fEB, Wp_e, 64,
                              nullptr, nullptr, 0, nullptr, NN);
        spmm_kernel<<<SB, 256>>>(fagg, fS, fR, i, 1, NN);
        mma_gemm<<<GB, 256>>>(fp, fp, puW, 64, fagg, puW + 64 * 64, 64,
                              nullptr, nullptr, 0, pu_b + i * 64, NN);
    }

    // ----- output: (h, p) concatenated -----
    out_kernel<<<ZB, 256>>>((float*)d_out);
}